// round 14
// baseline (speedup 1.0000x reference)
#include <cuda_runtime.h>
#include <math.h>

#define M_FILT 16
#define IMG    96
#define BATCH  16
#define S      88
#define SP     22
#define FIN    (M_FILT * SP * SP)   // 7744
#define HID    128
#define CLASSES 10

#define NTILES     3872              // 11*11*32  (tile = 8x8 pos, m-half, batch)
#define DEND_GRID  2368              // 148 SMs * 16 resident blocks

typedef unsigned long long u64;

__device__ float g_pool[BATCH * FIN];
__device__ float g_hidden[BATCH * HID];
__device__ unsigned int g_tile_ctr;

// ---- packed f32x2 helpers (sm_103a) ----
__device__ __forceinline__ u64 PK(float a, float b) {
    u64 r; asm("mov.b64 %0, {%1, %2};" : "=l"(r) : "f"(a), "f"(b)); return r;
}
__device__ __forceinline__ void UPK(u64 v, float& a, float& b) {
    asm("mov.b64 {%0, %1}, %2;" : "=f"(a), "=f"(b) : "l"(v));
}
__device__ __forceinline__ u64 FMA2(u64 a, u64 b, u64 c) {
    u64 d; asm("fma.rn.f32x2 %0, %1, %2, %3;" : "=l"(d) : "l"(a), "l"(b), "l"(c)); return d;
}
__device__ __forceinline__ u64 MUL2(u64 a, u64 b) {
    u64 d; asm("mul.rn.f32x2 %0, %1, %2;" : "=l"(d) : "l"(a), "l"(b)); return d;
}
__device__ __forceinline__ float RCPA(float x) {
    float r; asm("rcp.approx.ftz.f32 %0, %1;" : "=f"(r) : "f"(x)); return r;
}

// atan(z)/pi on z in [-1,1], deg-7 odd (|err| ~ 2.7e-5)
#define PC0  0.3180345f
#define PC1 -0.1020292f
#define PC2  0.0461483f
#define PC3 -0.0121772f

// Persistent: DEND_GRID blocks of 64 threads; tiles claimed via atomic counter.
__global__ __launch_bounds__(64, 16)
void dendrite_pool_kernel(const float* __restrict__ x,
                          const float* __restrict__ w,
                          const float* __restrict__ q) {
    __shared__ float2 xs2[16][17];           // padded row: conflict-free
    __shared__ float4 wq8[81 * 8];           // [tap][ml]: contiguous 128B per warp read
    __shared__ float  part[8][8][2];         // [li][m_local][jhalf]
    __shared__ unsigned s_tile;

    const int t  = threadIdx.x;
    const int ml = t & 7;
    const int li = t >> 3;

    const u64 K3   = PK(PC3, PC3);
    const u64 K2   = PK(PC2, PC2);
    const u64 K1   = PK(PC1, PC1);
    const u64 K0   = PK(PC0, PC0);
    const u64 QTR  = PK(0.25f, 0.25f);
    const u64 ONE1 = PK(1.0f, 1.0f);
    const u64 NEG2 = PK(-2.0f, -2.0f);
    const u64 C11  = PK(1.1f, 1.1f);

// arg = 1.1 + s*(0.25 + z*P(z^2)), z = 1 - 2/(s*u+1).
// ONE rcp per pair: rp = 1/(h0*h1); 1/h0 = rp*h1, 1/h1 = rp*h0.
#define GPAIR(X2, ACC) do {                                                    \
    u64 u_ = FMA2((X2), w2v, q2v);                                             \
    float u0_, u1_; UPK(u_, u0_, u1_);                                         \
    unsigned ub0_ = __float_as_uint(u0_), ub1_ = __float_as_uint(u1_);         \
    float sg0_ = __uint_as_float(0x3F800000u | (ub0_ & 0x80000000u));          \
    float sg1_ = __uint_as_float(0x3F800000u | (ub1_ & 0x80000000u));          \
    u64 s_ = PK(sg0_, sg1_);                                                   \
    u64 hp_ = FMA2(u_, s_, ONE1);            /* (|u0|+1, |u1|+1) */            \
    float h0_, h1_; UPK(hp_, h0_, h1_);                                        \
    float pr_ = h0_ * h1_;                                                     \
    float rp_ = RCPA(pr_);                                                     \
    float r0_ = rp_ * h1_;                   /* 1/h0 */                        \
    float r1_ = rp_ * h0_;                   /* 1/h1 */                        \
    u64 z_ = FMA2(NEG2, PK(r0_, r1_), ONE1);                                   \
    u64 z2_ = MUL2(z_, z_);                                                    \
    u64 P_  = FMA2(K3, z2_, K2);                                               \
    P_ = FMA2(P_, z2_, K1);                                                    \
    P_ = FMA2(P_, z2_, K0);                                                    \
    u64 B_ = FMA2(z_, P_, QTR);              /* B in [0, 0.5] */               \
    u64 arg_ = FMA2(s_, B_, C11);                                              \
    ACC = MUL2(ACC, arg_);                                                     \
} while (0)

    for (;;) {
        if (t == 0) s_tile = atomicAdd(&g_tile_ctr, 1u);
        __syncthreads();
        const unsigned tile = s_tile;
        if (tile >= NTILES) break;

        const int bz = tile / 121;
        const int rem = tile - bz * 121;
        const int by = rem / 11;
        const int bx = rem - by * 11;
        const int b  = bz >> 1;
        const int mh = (bz & 1) * 8;
        const int i0 = by * 8;
        const int j0 = bx * 8;

        for (int k = t; k < 256; k += 64) {
            int rr = k >> 4, cc = k & 15;
            if (cc < 15) {
                const float* xr = &x[(b * IMG + i0 + rr) * IMG + j0];
                xs2[rr][cc] = make_float2(xr[cc], xr[cc + 1]);
            }
        }
        for (int k = t; k < 81 * 8; k += 64) {
            int tap = k >> 3, mlk = k & 7;
            int g = (mh + mlk) * 81 + tap;
            float wv = 10.0f * w[g];
            float qv = -10.0f * q[g];
            wq8[k] = make_float4(wv, wv, qv, qv);
        }
        __syncthreads();

        u64 acc0 = ONE1, acc1 = ONE1, acc2 = ONE1, acc3 = ONE1;
        const float4* __restrict__ wqt = &wq8[ml];

        for (int r = 0; r < 9; ++r) {
            const u64* __restrict__ xrow = (const u64*)&xs2[li + r][0];
            u64 xp[8];
            #pragma unroll
            for (int k = 0; k < 7; ++k) xp[k] = xrow[k];
            #pragma unroll
            for (int c = 0; c < 9; ++c) {
                if (c < 8) xp[(c + 7) & 7] = xrow[c + 7];
                float4 wqv = wqt[(r * 9 + c) * 8];
                u64 w2v = PK(wqv.x, wqv.y);
                u64 q2v = PK(wqv.z, wqv.w);
                GPAIR(xp[c & 7],       acc0);
                GPAIR(xp[(c + 2) & 7], acc1);
                GPAIR(xp[(c + 4) & 7], acc2);
                GPAIR(xp[(c + 6) & 7], acc3);
            }
        }

        float a0, a1, b0, b1, c0, c1, d0, d1;
        UPK(acc0, a0, a1); UPK(acc1, b0, b1);
        UPK(acc2, c0, c1); UPK(acc3, d0, d1);
        part[li][ml][0] = fmaxf(fmaxf(a0, a1), fmaxf(b0, b1));
        part[li][ml][1] = fmaxf(fmaxf(c0, c1), fmaxf(d0, d1));
        __syncthreads();

        if (t < 32) {
            const int m2   = t & 7;
            const int cell = t >> 3;
            const int ip   = cell >> 1;
            const int jp   = cell & 1;
            const int r0   = 4 * ip;
            float v = fmaxf(fmaxf(part[r0][m2][jp],     part[r0 + 1][m2][jp]),
                            fmaxf(part[r0 + 2][m2][jp], part[r0 + 3][m2][jp]));
            const int gip = 2 * by + ip;
            const int gjp = 2 * bx + jp;
            g_pool[((b * SP + gip) * SP + gjp) * M_FILT + mh + m2] = __logf(v);
        }
        __syncthreads();      // smem safe for next tile
    }
#undef GPAIR
}

// FC1: one warp per (b, o); 2048 warps over 256 blocks. 4-way unroll, deep MLP.
__global__ __launch_bounds__(256)
void fc1_kernel(const float* __restrict__ W, const float* __restrict__ bias) {
    const int warp = (blockIdx.x * blockDim.x + threadIdx.x) >> 5;
    const int lane = threadIdx.x & 31;
    const int b = warp >> 7;
    const int o = warp & 127;
    const float4* __restrict__ ip = (const float4*)(g_pool + b * FIN);
    const float4* __restrict__ wp = (const float4*)(W + o * FIN);
    float s0 = 0.f, s1 = 0.f, s2 = 0.f, s3 = 0.f;
    // FIN/4 = 1936 = 128*15 + 16
    int k = lane;
    #pragma unroll 1
    for (int it = 0; it < 15; ++it, k += 128) {
        float4 a0 = ip[k],      v0 = wp[k];
        float4 a1 = ip[k + 32], v1 = wp[k + 32];
        float4 a2 = ip[k + 64], v2 = wp[k + 64];
        float4 a3 = ip[k + 96], v3 = wp[k + 96];
        s0 = fmaf(a0.x, v0.x, s0); s0 = fmaf(a0.y, v0.y, s0);
        s0 = fmaf(a0.z, v0.z, s0); s0 = fmaf(a0.w, v0.w, s0);
        s1 = fmaf(a1.x, v1.x, s1); s1 = fmaf(a1.y, v1.y, s1);
        s1 = fmaf(a1.z, v1.z, s1); s1 = fmaf(a1.w, v1.w, s1);
        s2 = fmaf(a2.x, v2.x, s2); s2 = fmaf(a2.y, v2.y, s2);
        s2 = fmaf(a2.z, v2.z, s2); s2 = fmaf(a2.w, v2.w, s2);
        s3 = fmaf(a3.x, v3.x, s3); s3 = fmaf(a3.y, v3.y, s3);
        s3 = fmaf(a3.z, v3.z, s3); s3 = fmaf(a3.w, v3.w, s3);
    }
    if (k < FIN / 4) {        // tail: 16 float4s, lanes 0..15
        float4 a0 = ip[k], v0 = wp[k];
        s0 = fmaf(a0.x, v0.x, s0); s0 = fmaf(a0.y, v0.y, s0);
        s0 = fmaf(a0.z, v0.z, s0); s0 = fmaf(a0.w, v0.w, s0);
    }
    float s = (s0 + s1) + (s2 + s3);
    #pragma unroll
    for (int off = 16; off; off >>= 1) s += __shfl_down_sync(0xFFFFFFFFu, s, off);
    if (lane == 0) g_hidden[b * HID + o] = fmaxf(s + bias[o], 0.f);
}

__global__ __launch_bounds__(320)
void fc2_kernel(const float* __restrict__ W, const float* __restrict__ bias,
                float* __restrict__ out) {
    const int b    = blockIdx.x;
    const int warp = threadIdx.x >> 5;
    const int lane = threadIdx.x & 31;
    const float* __restrict__ h  = g_hidden + b * HID;
    const float* __restrict__ wp = W + warp * HID;
    float s = 0.f;
    #pragma unroll
    for (int k = lane; k < HID; k += 32) s = fmaf(h[k], wp[k], s);
    #pragma unroll
    for (int off = 16; off; off >>= 1) s += __shfl_down_sync(0xFFFFFFFFu, s, off);
    if (lane == 0) out[b * CLASSES + warp] = s + bias[warp];
}

extern "C" void kernel_launch(void* const* d_in, const int* in_sizes, int n_in,
                              void* d_out, int out_size) {
    const float* x     = (const float*)d_in[0];
    const float* w     = (const float*)d_in[1];
    const float* q     = (const float*)d_in[2];
    const float* fc1_w = (const float*)d_in[3];
    const float* fc1_b = (const float*)d_in[4];
    const float* fc2_w = (const float*)d_in[5];
    const float* fc2_b = (const float*)d_in[6];
    float* out = (float*)d_out;

    void* ctr_addr = nullptr;
    cudaGetSymbolAddress(&ctr_addr, g_tile_ctr);
    cudaMemsetAsync(ctr_addr, 0, sizeof(unsigned int), 0);

    dendrite_pool_kernel<<<DEND_GRID, 64>>>(x, w, q);
    fc1_kernel<<<256, 256>>>(fc1_w, fc1_b);
    fc2_kernel<<<BATCH, 320>>>(fc2_w, fc2_b, out);
}

// round 15
// speedup vs baseline: 1.1094x; 1.1094x over previous
#include <cuda_runtime.h>
#include <math.h>

#define M_FILT 16
#define IMG    96
#define BATCH  16
#define S      88
#define SP     22
#define FIN    (M_FILT * SP * SP)   // 7744
#define HID    128
#define CLASSES 10

#define NTILES     3872              // 11*11*32
#define DEND_GRID  2368              // 148 SMs * 16 resident blocks

typedef unsigned long long u64;

__device__ float g_pool[BATCH * FIN];
__device__ float g_hidden[BATCH * HID];
__device__ unsigned int g_tile_ctr;

// ---- packed f32x2 helpers (sm_103a) ----
__device__ __forceinline__ u64 PK(float a, float b) {
    u64 r; asm("mov.b64 %0, {%1, %2};" : "=l"(r) : "f"(a), "f"(b)); return r;
}
__device__ __forceinline__ void UPK(u64 v, float& a, float& b) {
    asm("mov.b64 {%0, %1}, %2;" : "=f"(a), "=f"(b) : "l"(v));
}
__device__ __forceinline__ u64 FMA2(u64 a, u64 b, u64 c) {
    u64 d; asm("fma.rn.f32x2 %0, %1, %2, %3;" : "=l"(d) : "l"(a), "l"(b), "l"(c)); return d;
}
__device__ __forceinline__ u64 MUL2(u64 a, u64 b) {
    u64 d; asm("mul.rn.f32x2 %0, %1, %2;" : "=l"(d) : "l"(a), "l"(b)); return d;
}
__device__ __forceinline__ float RCPA(float x) {
    float r; asm("rcp.approx.ftz.f32 %0, %1;" : "=f"(r) : "f"(x)); return r;
}

// atan(z)/pi on z in [-1,1], deg-5 odd minimax (|err| ~ 6.5e-4 rad -> 2.1e-4 in arg)
#define PC0  0.31681737f
#define PC1 -0.09191320f
#define PC2  0.02525128f

// Persistent: DEND_GRID blocks of 64 threads; tiles claimed via atomic counter.
__global__ __launch_bounds__(64, 16)
void dendrite_pool_kernel(const float* __restrict__ x,
                          const float* __restrict__ w,
                          const float* __restrict__ q) {
    __shared__ float2 xs2[16][17];           // padded row: conflict-free
    __shared__ float4 wq8[81 * 8];           // [tap][ml]: contiguous 128B per warp read
    __shared__ float  part[8][8][2];         // [li][m_local][jhalf]
    __shared__ unsigned s_tile;

    const int t  = threadIdx.x;
    const int ml = t & 7;
    const int li = t >> 3;

    const u64 K2   = PK(PC2, PC2);
    const u64 K1   = PK(PC1, PC1);
    const u64 K0   = PK(PC0, PC0);
    const u64 QTR  = PK(0.25f, 0.25f);
    const u64 ONE1 = PK(1.0f, 1.0f);
    const u64 NEG2 = PK(-2.0f, -2.0f);
    const u64 C11  = PK(1.1f, 1.1f);

// arg = 1.1 + s*(0.25 + z*P(z^2)),  s = +-1,  z = 1 - 2/(s*u + 1)
#define GPAIR(X2, ACC) do {                                                    \
    u64 u_ = FMA2((X2), w2v, q2v);                                             \
    float u0_, u1_; UPK(u_, u0_, u1_);                                         \
    unsigned ub0_ = __float_as_uint(u0_), ub1_ = __float_as_uint(u1_);         \
    float sg0_ = __uint_as_float(0x3F800000u | (ub0_ & 0x80000000u));          \
    float sg1_ = __uint_as_float(0x3F800000u | (ub1_ & 0x80000000u));          \
    u64 s_ = PK(sg0_, sg1_);                                                   \
    u64 hp_ = FMA2(u_, s_, ONE1);            /* |u| + 1 >= 1 */                \
    float h0_, h1_; UPK(hp_, h0_, h1_);                                        \
    float r0_ = RCPA(h0_), r1_ = RCPA(h1_);                                    \
    u64 z_ = FMA2(NEG2, PK(r0_, r1_), ONE1);                                   \
    u64 z2_ = MUL2(z_, z_);                                                    \
    u64 P_  = FMA2(K2, z2_, K1);                                               \
    P_ = FMA2(P_, z2_, K0);                                                    \
    u64 B_ = FMA2(z_, P_, QTR);              /* B in [0, 0.5] */               \
    u64 arg_ = FMA2(s_, B_, C11);                                              \
    ACC = MUL2(ACC, arg_);                                                     \
} while (0)

    for (;;) {
        if (t == 0) s_tile = atomicAdd(&g_tile_ctr, 1u);
        __syncthreads();
        const unsigned tile = s_tile;
        if (tile >= NTILES) break;

        const int bz = tile / 121;
        const int rem = tile - bz * 121;
        const int by = rem / 11;
        const int bx = rem - by * 11;
        const int b  = bz >> 1;
        const int mh = (bz & 1) * 8;
        const int i0 = by * 8;
        const int j0 = bx * 8;

        for (int k = t; k < 256; k += 64) {
            int rr = k >> 4, cc = k & 15;
            if (cc < 15) {
                const float* xr = &x[(b * IMG + i0 + rr) * IMG + j0];
                xs2[rr][cc] = make_float2(xr[cc], xr[cc + 1]);
            }
        }
        for (int k = t; k < 81 * 8; k += 64) {
            int tap = k >> 3, mlk = k & 7;
            int g = (mh + mlk) * 81 + tap;
            float wv = 10.0f * w[g];
            float qv = -10.0f * q[g];
            wq8[k] = make_float4(wv, wv, qv, qv);
        }
        __syncthreads();

        u64 acc0 = ONE1, acc1 = ONE1, acc2 = ONE1, acc3 = ONE1;
        const float4* __restrict__ wqt = &wq8[ml];

        for (int r = 0; r < 9; ++r) {
            const u64* __restrict__ xrow = (const u64*)&xs2[li + r][0];
            u64 xp[8];
            #pragma unroll
            for (int k = 0; k < 7; ++k) xp[k] = xrow[k];
            #pragma unroll
            for (int c = 0; c < 9; ++c) {
                if (c < 8) xp[(c + 7) & 7] = xrow[c + 7];
                float4 wqv = wqt[(r * 9 + c) * 8];
                u64 w2v = PK(wqv.x, wqv.y);
                u64 q2v = PK(wqv.z, wqv.w);
                GPAIR(xp[c & 7],       acc0);
                GPAIR(xp[(c + 2) & 7], acc1);
                GPAIR(xp[(c + 4) & 7], acc2);
                GPAIR(xp[(c + 6) & 7], acc3);
            }
        }

        float a0, a1, b0, b1, c0, c1, d0, d1;
        UPK(acc0, a0, a1); UPK(acc1, b0, b1);
        UPK(acc2, c0, c1); UPK(acc3, d0, d1);
        part[li][ml][0] = fmaxf(fmaxf(a0, a1), fmaxf(b0, b1));
        part[li][ml][1] = fmaxf(fmaxf(c0, c1), fmaxf(d0, d1));
        __syncthreads();

        if (t < 32) {
            const int m2   = t & 7;
            const int cell = t >> 3;
            const int ip   = cell >> 1;
            const int jp   = cell & 1;
            const int r0   = 4 * ip;
            float v = fmaxf(fmaxf(part[r0][m2][jp],     part[r0 + 1][m2][jp]),
                            fmaxf(part[r0 + 2][m2][jp], part[r0 + 3][m2][jp]));
            const int gip = 2 * by + ip;
            const int gjp = 2 * bx + jp;
            g_pool[((b * SP + gip) * SP + gjp) * M_FILT + mh + m2] = __logf(v);
        }
        __syncthreads();      // smem safe for next tile
    }
#undef GPAIR
}

// FC1: one warp per (b, o); 2048 warps over 256 blocks. 4-way unroll, deep MLP.
__global__ __launch_bounds__(256)
void fc1_kernel(const float* __restrict__ W, const float* __restrict__ bias) {
    const int warp = (blockIdx.x * blockDim.x + threadIdx.x) >> 5;
    const int lane = threadIdx.x & 31;
    const int b = warp >> 7;
    const int o = warp & 127;
    const float4* __restrict__ ip = (const float4*)(g_pool + b * FIN);
    const float4* __restrict__ wp = (const float4*)(W + o * FIN);
    float s0 = 0.f, s1 = 0.f, s2 = 0.f, s3 = 0.f;
    int k = lane;
    #pragma unroll 1
    for (int it = 0; it < 15; ++it, k += 128) {
        float4 a0 = ip[k],      v0 = wp[k];
        float4 a1 = ip[k + 32], v1 = wp[k + 32];
        float4 a2 = ip[k + 64], v2 = wp[k + 64];
        float4 a3 = ip[k + 96], v3 = wp[k + 96];
        s0 = fmaf(a0.x, v0.x, s0); s0 = fmaf(a0.y, v0.y, s0);
        s0 = fmaf(a0.z, v0.z, s0); s0 = fmaf(a0.w, v0.w, s0);
        s1 = fmaf(a1.x, v1.x, s1); s1 = fmaf(a1.y, v1.y, s1);
        s1 = fmaf(a1.z, v1.z, s1); s1 = fmaf(a1.w, v1.w, s1);
        s2 = fmaf(a2.x, v2.x, s2); s2 = fmaf(a2.y, v2.y, s2);
        s2 = fmaf(a2.z, v2.z, s2); s2 = fmaf(a2.w, v2.w, s2);
        s3 = fmaf(a3.x, v3.x, s3); s3 = fmaf(a3.y, v3.y, s3);
        s3 = fmaf(a3.z, v3.z, s3); s3 = fmaf(a3.w, v3.w, s3);
    }
    if (k < FIN / 4) {
        float4 a0 = ip[k], v0 = wp[k];
        s0 = fmaf(a0.x, v0.x, s0); s0 = fmaf(a0.y, v0.y, s0);
        s0 = fmaf(a0.z, v0.z, s0); s0 = fmaf(a0.w, v0.w, s0);
    }
    float s = (s0 + s1) + (s2 + s3);
    #pragma unroll
    for (int off = 16; off; off >>= 1) s += __shfl_down_sync(0xFFFFFFFFu, s, off);
    if (lane == 0) g_hidden[b * HID + o] = fmaxf(s + bias[o], 0.f);
}

__global__ __launch_bounds__(320)
void fc2_kernel(const float* __restrict__ W, const float* __restrict__ bias,
                float* __restrict__ out) {
    const int b    = blockIdx.x;
    const int warp = threadIdx.x >> 5;
    const int lane = threadIdx.x & 31;
    const float* __restrict__ h  = g_hidden + b * HID;
    const float* __restrict__ wp = W + warp * HID;
    float s = 0.f;
    #pragma unroll
    for (int k = lane; k < HID; k += 32) s = fmaf(h[k], wp[k], s);
    #pragma unroll
    for (int off = 16; off; off >>= 1) s += __shfl_down_sync(0xFFFFFFFFu, s, off);
    if (lane == 0) out[b * CLASSES + warp] = s + bias[warp];
}

extern "C" void kernel_launch(void* const* d_in, const int* in_sizes, int n_in,
                              void* d_out, int out_size) {
    const float* x     = (const float*)d_in[0];
    const float* w     = (const float*)d_in[1];
    const float* q     = (const float*)d_in[2];
    const float* fc1_w = (const float*)d_in[3];
    const float* fc1_b = (const float*)d_in[4];
    const float* fc2_w = (const float*)d_in[5];
    const float* fc2_b = (const float*)d_in[6];
    float* out = (float*)d_out;

    void* ctr_addr = nullptr;
    cudaGetSymbolAddress(&ctr_addr, g_tile_ctr);
    cudaMemsetAsync(ctr_addr, 0, sizeof(unsigned int), 0);

    dendrite_pool_kernel<<<DEND_GRID, 64>>>(x, w, q);
    fc1_kernel<<<256, 256>>>(fc1_w, fc1_b);
    fc2_kernel<<<BATCH, 320>>>(fc2_w, fc2_b, out);
}

// round 16
// speedup vs baseline: 1.2349x; 1.1131x over previous
#include <cuda_runtime.h>
#include <math.h>

#define M_FILT 16
#define IMG    96
#define BATCH  16
#define S      88
#define SP     22
#define FIN    (M_FILT * SP * SP)   // 7744
#define HID    128
#define CLASSES 10

#define NTILES     3872              // 11*11*32
#define DEND_GRID  2368              // 148 SMs * 16 resident blocks

typedef unsigned long long u64;

__device__ float g_pool[BATCH * FIN];
__device__ float g_hidden[BATCH * HID];
__device__ unsigned int g_tile_ctr;

// ---- packed f32x2 helpers (sm_103a) ----
__device__ __forceinline__ u64 PK(float a, float b) {
    u64 r; asm("mov.b64 %0, {%1, %2};" : "=l"(r) : "f"(a), "f"(b)); return r;
}
__device__ __forceinline__ void UPK(u64 v, float& a, float& b) {
    asm("mov.b64 {%0, %1}, %2;" : "=f"(a), "=f"(b) : "l"(v));
}
__device__ __forceinline__ u64 FMA2(u64 a, u64 b, u64 c) {
    u64 d; asm("fma.rn.f32x2 %0, %1, %2, %3;" : "=l"(d) : "l"(a), "l"(b), "l"(c)); return d;
}
__device__ __forceinline__ u64 MUL2(u64 a, u64 b) {
    u64 d; asm("mul.rn.f32x2 %0, %1, %2;" : "=l"(d) : "l"(a), "l"(b)); return d;
}
__device__ __forceinline__ float RCPA(float x) {
    float r; asm("rcp.approx.ftz.f32 %0, %1;" : "=f"(r) : "f"(x)); return r;
}

// atan(z)/pi on z in [-1,1], deg-7 odd (|err| ~ 2.7e-5 in arg)
#define PC0  0.3180345f
#define PC1 -0.1020292f
#define PC2  0.0461483f
#define PC3 -0.0121772f

// Persistent: DEND_GRID blocks of 64 threads; tiles claimed via atomic counter.
__global__ __launch_bounds__(64, 16)
void dendrite_pool_kernel(const float* __restrict__ x,
                          const float* __restrict__ w,
                          const float* __restrict__ q) {
    __shared__ float2 xs2[16][17];           // padded row: conflict-free
    __shared__ float4 wq8[81 * 8];           // [tap][ml]: contiguous 128B per warp read
    __shared__ float  part[8][8][2];         // [li][m_local][jhalf]
    __shared__ unsigned s_tile;

    const int t  = threadIdx.x;
    const int ml = t & 7;
    const int li = t >> 3;

    const u64 K3   = PK(PC3, PC3);
    const u64 K2   = PK(PC2, PC2);
    const u64 K1   = PK(PC1, PC1);
    const u64 K0   = PK(PC0, PC0);
    const u64 QTR  = PK(0.25f, 0.25f);
    const u64 ONE1 = PK(1.0f, 1.0f);
    const u64 NEG2 = PK(-2.0f, -2.0f);
    const u64 C11  = PK(1.1f, 1.1f);

// arg = 1.1 + s*(0.25 + z*P(z^2)),  s = +-1,  z = 1 - 2/(s*u + 1)
#define GPAIR(X2, ACC) do {                                                    \
    u64 u_ = FMA2((X2), w2v, q2v);                                             \
    float u0_, u1_; UPK(u_, u0_, u1_);                                         \
    unsigned ub0_ = __float_as_uint(u0_), ub1_ = __float_as_uint(u1_);         \
    float sg0_ = __uint_as_float(0x3F800000u | (ub0_ & 0x80000000u));          \
    float sg1_ = __uint_as_float(0x3F800000u | (ub1_ & 0x80000000u));          \
    u64 s_ = PK(sg0_, sg1_);                                                   \
    u64 hp_ = FMA2(u_, s_, ONE1);            /* |u| + 1 >= 1 */                \
    float h0_, h1_; UPK(hp_, h0_, h1_);                                        \
    float r0_ = RCPA(h0_), r1_ = RCPA(h1_);                                    \
    u64 z_ = FMA2(NEG2, PK(r0_, r1_), ONE1);                                   \
    u64 z2_ = MUL2(z_, z_);                                                    \
    u64 P_  = FMA2(K3, z2_, K2);                                               \
    P_ = FMA2(P_, z2_, K1);                                                    \
    P_ = FMA2(P_, z2_, K0);                                                    \
    u64 B_ = FMA2(z_, P_, QTR);              /* B in [0, 0.5] */               \
    u64 arg_ = FMA2(s_, B_, C11);                                              \
    ACC = MUL2(ACC, arg_);                                                     \
} while (0)

    for (;;) {
        if (t == 0) s_tile = atomicAdd(&g_tile_ctr, 1u);
        __syncthreads();
        const unsigned tile = s_tile;
        if (tile >= NTILES) break;

        const int bz = tile / 121;
        const int rem = tile - bz * 121;
        const int by = rem / 11;
        const int bx = rem - by * 11;
        const int b  = bz >> 1;
        const int mh = (bz & 1) * 8;
        const int i0 = by * 8;
        const int j0 = bx * 8;

        for (int k = t; k < 256; k += 64) {
            int rr = k >> 4, cc = k & 15;
            if (cc < 15) {
                const float* xr = &x[(b * IMG + i0 + rr) * IMG + j0];
                xs2[rr][cc] = make_float2(xr[cc], xr[cc + 1]);
            }
        }
        for (int k = t; k < 81 * 8; k += 64) {
            int tap = k >> 3, mlk = k & 7;
            int g = (mh + mlk) * 81 + tap;
            float wv = 10.0f * w[g];
            float qv = -10.0f * q[g];
            wq8[k] = make_float4(wv, wv, qv, qv);
        }
        __syncthreads();

        u64 acc0 = ONE1, acc1 = ONE1, acc2 = ONE1, acc3 = ONE1;
        const float4* __restrict__ wqt = &wq8[ml];

        for (int r = 0; r < 9; ++r) {
            const u64* __restrict__ xrow = (const u64*)&xs2[li + r][0];
            u64 xp[8];
            #pragma unroll
            for (int k = 0; k < 7; ++k) xp[k] = xrow[k];
            #pragma unroll
            for (int c = 0; c < 9; ++c) {
                if (c < 8) xp[(c + 7) & 7] = xrow[c + 7];
                float4 wqv = wqt[(r * 9 + c) * 8];
                u64 w2v = PK(wqv.x, wqv.y);
                u64 q2v = PK(wqv.z, wqv.w);
                GPAIR(xp[c & 7],       acc0);
                GPAIR(xp[(c + 2) & 7], acc1);
                GPAIR(xp[(c + 4) & 7], acc2);
                GPAIR(xp[(c + 6) & 7], acc3);
            }
        }

        float a0, a1, b0, b1, c0, c1, d0, d1;
        UPK(acc0, a0, a1); UPK(acc1, b0, b1);
        UPK(acc2, c0, c1); UPK(acc3, d0, d1);
        part[li][ml][0] = fmaxf(fmaxf(a0, a1), fmaxf(b0, b1));
        part[li][ml][1] = fmaxf(fmaxf(c0, c1), fmaxf(d0, d1));
        __syncthreads();

        if (t < 32) {
            const int m2   = t & 7;
            const int cell = t >> 3;
            const int ip   = cell >> 1;
            const int jp   = cell & 1;
            const int r0   = 4 * ip;
            float v = fmaxf(fmaxf(part[r0][m2][jp],     part[r0 + 1][m2][jp]),
                            fmaxf(part[r0 + 2][m2][jp], part[r0 + 3][m2][jp]));
            const int gip = 2 * by + ip;
            const int gjp = 2 * bx + jp;
            g_pool[((b * SP + gip) * SP + gjp) * M_FILT + mh + m2] = __logf(v);
        }
        __syncthreads();      // smem safe for next tile
    }
#undef GPAIR
}

// FC1: one BLOCK per (b, o); 2048 blocks x 128 threads. Per-thread serial
// depth = 16 float4 loads (vs 60 warp-per-output). Two-stage reduction.
__global__ __launch_bounds__(128)
void fc1_kernel(const float* __restrict__ W, const float* __restrict__ bias) {
    __shared__ float wsum[4];
    const int b = blockIdx.x >> 7;
    const int o = blockIdx.x & 127;
    const int t = threadIdx.x;
    const int lane = t & 31;
    const int warp = t >> 5;

    const float4* __restrict__ ip = (const float4*)(g_pool + b * FIN);
    const float4* __restrict__ wp = (const float4*)(W + o * FIN);

    float s0 = 0.f, s1 = 0.f;
    // FIN/4 = 1936 = 128*15 + 16; split as two interleaved halves for MLP
    int k = t;
    #pragma unroll 1
    for (int it = 0; it < 7; ++it, k += 256) {
        float4 a0 = ip[k],       v0 = wp[k];
        float4 a1 = ip[k + 128], v1 = wp[k + 128];
        s0 = fmaf(a0.x, v0.x, s0); s0 = fmaf(a0.y, v0.y, s0);
        s0 = fmaf(a0.z, v0.z, s0); s0 = fmaf(a0.w, v0.w, s0);
        s1 = fmaf(a1.x, v1.x, s1); s1 = fmaf(a1.y, v1.y, s1);
        s1 = fmaf(a1.z, v1.z, s1); s1 = fmaf(a1.w, v1.w, s1);
    }
    // k = t + 1792; remaining indices 1792..1935 (144 float4s): threads 0..143 -> 128 + 16
    if (k < FIN / 4) {
        float4 a0 = ip[k], v0 = wp[k];
        s0 = fmaf(a0.x, v0.x, s0); s0 = fmaf(a0.y, v0.y, s0);
        s0 = fmaf(a0.z, v0.z, s0); s0 = fmaf(a0.w, v0.w, s0);
    }
    k += 128;
    if (k < FIN / 4) {
        float4 a1 = ip[k], v1 = wp[k];
        s1 = fmaf(a1.x, v1.x, s1); s1 = fmaf(a1.y, v1.y, s1);
        s1 = fmaf(a1.z, v1.z, s1); s1 = fmaf(a1.w, v1.w, s1);
    }
    float s = s0 + s1;
    #pragma unroll
    for (int off = 16; off; off >>= 1) s += __shfl_down_sync(0xFFFFFFFFu, s, off);
    if (lane == 0) wsum[warp] = s;
    __syncthreads();
    if (t == 0) {
        float tot = (wsum[0] + wsum[1]) + (wsum[2] + wsum[3]);
        g_hidden[b * HID + o] = fmaxf(tot + bias[o], 0.f);
    }
}

__global__ __launch_bounds__(320)
void fc2_kernel(const float* __restrict__ W, const float* __restrict__ bias,
                float* __restrict__ out) {
    const int b    = blockIdx.x;
    const int warp = threadIdx.x >> 5;
    const int lane = threadIdx.x & 31;
    const float* __restrict__ h  = g_hidden + b * HID;
    const float* __restrict__ wp = W + warp * HID;
    float s = 0.f;
    #pragma unroll
    for (int k = lane; k < HID; k += 32) s = fmaf(h[k], wp[k], s);
    #pragma unroll
    for (int off = 16; off; off >>= 1) s += __shfl_down_sync(0xFFFFFFFFu, s, off);
    if (lane == 0) out[b * CLASSES + warp] = s + bias[warp];
}

extern "C" void kernel_launch(void* const* d_in, const int* in_sizes, int n_in,
                              void* d_out, int out_size) {
    const float* x     = (const float*)d_in[0];
    const float* w     = (const float*)d_in[1];
    const float* q     = (const float*)d_in[2];
    const float* fc1_w = (const float*)d_in[3];
    const float* fc1_b = (const float*)d_in[4];
    const float* fc2_w = (const float*)d_in[5];
    const float* fc2_b = (const float*)d_in[6];
    float* out = (float*)d_out;

    void* ctr_addr = nullptr;
    cudaGetSymbolAddress(&ctr_addr, g_tile_ctr);
    cudaMemsetAsync(ctr_addr, 0, sizeof(unsigned int), 0);

    dendrite_pool_kernel<<<DEND_GRID, 64>>>(x, w, q);
    fc1_kernel<<<BATCH * HID, 128>>>(fc1_w, fc1_b);
    fc2_kernel<<<BATCH, 320>>>(fc2_w, fc2_b, out);
}